// round 1
// baseline (speedup 1.0000x reference)
#include <cuda_runtime.h>

// Problem dims
#define BATCH 512
#define SEQT  512
#define IDIM  64
#define HDIM  256
#define KDIM  (HDIM + IDIM)     // 320: concatenated [h | x_t]

// Tiling
#define MB_GROUPS 8             // batch groups
#define JB_GROUPS 16            // hidden-unit groups
#define MTILE 64                // batch rows per group
#define JTILE 16                // hidden units per CTA
#define WROWS (3 * JTILE)       // 48 gate rows per CTA (r,z,n per unit)
#define NTH 128                 // threads per CTA
#define HP 324                  // smem pitch (320 + 4): float4-aligned, conflict-free

// Persistent device scratch (no cudaMalloc allowed)
__device__ float    g_h[2][BATCH * HDIM];   // ping-pong hidden state
__device__ unsigned g_cnt[MB_GROUPS];       // per-group barrier counters
__device__ unsigned g_gen[MB_GROUPS];       // per-group barrier generations (monotone)

__device__ __forceinline__ float sigmoidf_fast(float v) {
    return 1.0f / (1.0f + __expf(-v));
}

__global__ void __launch_bounds__(NTH, 1) gru_fused_kernel(
    const float* __restrict__ x,      // [B, T, I]
    const float* __restrict__ w_ih,   // [3H, I]
    const float* __restrict__ w_hh,   // [3H, H]
    const float* __restrict__ b_ih,   // [3H]
    const float* __restrict__ b_hh,   // [3H]
    const float* __restrict__ w_lin,  // [1, H]
    const float* __restrict__ b_lin,  // [1]
    float* __restrict__ out)          // [2B]
{
    extern __shared__ float smem[];
    float* h_sm = smem;                    // [MTILE][HP]: cols 0..255 = h, 256..319 = x_t
    float* w_sm = smem + MTILE * HP;       // [WROWS][HP]: cols 0..255 = w_hh, 256..319 = w_ih

    const int tid = threadIdx.x;
    const int jb  = blockIdx.x;            // 0..15 hidden group
    const int mb  = blockIdx.y;            // 0..7  batch group
    const int ug  = tid & 7;               // unit-group lane (0..7)
    const int rg  = tid >> 3;              // row-group (0..15)

    // ---- Load this CTA's weight slice into SMEM once (persists for all 512 steps) ----
    // Local gate-row rr = u*3 + g maps to global weight row g*HDIM + jb*JTILE + u.
    for (int idx = tid; idx < WROWS * 80; idx += NTH) {
        int rr = idx / 80;
        int c4 = idx - rr * 80;            // float4 column index within 320
        int u  = rr / 3;
        int g  = rr - u * 3;
        int grow = g * HDIM + jb * JTILE + u;
        float4 v;
        if (c4 < 64)
            v = *(const float4*)(w_hh + (size_t)grow * HDIM + c4 * 4);
        else
            v = *(const float4*)(w_ih + (size_t)grow * IDIM + (c4 - 64) * 4);
        *(float4*)(w_sm + rr * HP + c4 * 4) = v;
    }

    // ---- Per-thread biases (r/z biases combine; n-gate biases must stay split) ----
    float bR[2], bZ[2], bIN[2], bHN[2];
#pragma unroll
    for (int j = 0; j < 2; j++) {
        int gi  = jb * JTILE + ug + 8 * j;
        bR[j]  = b_ih[gi] + b_hh[gi];
        bZ[j]  = b_ih[HDIM + gi] + b_hh[HDIM + gi];
        bIN[j] = b_ih[2 * HDIM + gi];
        bHN[j] = b_hh[2 * HDIM + gi];
    }

    // Quiescent barrier-generation base (stable: no concurrent writers at launch).
    const unsigned bar_base = *(volatile unsigned*)&g_gen[mb];
    unsigned bar_i = 0;

    __syncthreads();

    const size_t xrowstride = (size_t)SEQT * IDIM;
    const float* xblk = x + (size_t)(mb * MTILE) * xrowstride;

    for (int t = 0; t < SEQT; ++t) {
        // ---- Stage x_t tile into h_sm[:, 256:320] ----
        {
            const float* xbase = xblk + (size_t)t * IDIM;
            for (int idx = tid; idx < MTILE * 16; idx += NTH) {
                int row = idx >> 4, c4 = idx & 15;
                float4 v = __ldg((const float4*)(xbase + (size_t)row * xrowstride + c4 * 4));
                *(float4*)(h_sm + row * HP + HDIM + c4 * 4) = v;
            }
        }
        // ---- Stage h tile into h_sm[:, 0:256] (skip at t=0: h0 == 0) ----
        if (t > 0) {
            const float* hbase = g_h[t & 1] + (size_t)(mb * MTILE) * HDIM;
            for (int idx = tid; idx < MTILE * 64; idx += NTH) {
                int row = idx >> 6, c4 = idx & 63;
                float4 v = __ldcg((const float4*)(hbase + row * HDIM + c4 * 4));
                *(float4*)(h_sm + row * HP + c4 * 4) = v;
            }
        }
        __syncthreads();

        // ---- Register-tiled GEMM: 4 rows x 2 units x 3 gates per thread ----
        float accR[4][2], accZ[4][2], accHN[4][2], accXN[4][2];
#pragma unroll
        for (int i = 0; i < 4; i++)
#pragma unroll
            for (int j = 0; j < 2; j++) {
                accR[i][j] = 0.f; accZ[i][j] = 0.f; accHN[i][j] = 0.f; accXN[i][j] = 0.f;
            }

        const float* hr = h_sm + rg * HP;
        const float* w0 = w_sm + (ug * 3) * HP;        // unit ug
        const float* w1 = w_sm + ((ug + 8) * 3) * HP;  // unit ug+8

        if (t > 0) {
#pragma unroll 2
            for (int k = 0; k < HDIM; k += 4) {
                float4 hv[4];
                hv[0] = *(const float4*)(hr + k);
                hv[1] = *(const float4*)(hr + 16 * HP + k);
                hv[2] = *(const float4*)(hr + 32 * HP + k);
                hv[3] = *(const float4*)(hr + 48 * HP + k);
                float4 wv[2][3];
                wv[0][0] = *(const float4*)(w0 + k);
                wv[0][1] = *(const float4*)(w0 + HP + k);
                wv[0][2] = *(const float4*)(w0 + 2 * HP + k);
                wv[1][0] = *(const float4*)(w1 + k);
                wv[1][1] = *(const float4*)(w1 + HP + k);
                wv[1][2] = *(const float4*)(w1 + 2 * HP + k);
#pragma unroll
                for (int i = 0; i < 4; i++) {
                    const float4 h4 = hv[i];
#pragma unroll
                    for (int j = 0; j < 2; j++) {
                        accR[i][j]  = fmaf(h4.x, wv[j][0].x, accR[i][j]);
                        accR[i][j]  = fmaf(h4.y, wv[j][0].y, accR[i][j]);
                        accR[i][j]  = fmaf(h4.z, wv[j][0].z, accR[i][j]);
                        accR[i][j]  = fmaf(h4.w, wv[j][0].w, accR[i][j]);
                        accZ[i][j]  = fmaf(h4.x, wv[j][1].x, accZ[i][j]);
                        accZ[i][j]  = fmaf(h4.y, wv[j][1].y, accZ[i][j]);
                        accZ[i][j]  = fmaf(h4.z, wv[j][1].z, accZ[i][j]);
                        accZ[i][j]  = fmaf(h4.w, wv[j][1].w, accZ[i][j]);
                        accHN[i][j] = fmaf(h4.x, wv[j][2].x, accHN[i][j]);
                        accHN[i][j] = fmaf(h4.y, wv[j][2].y, accHN[i][j]);
                        accHN[i][j] = fmaf(h4.z, wv[j][2].z, accHN[i][j]);
                        accHN[i][j] = fmaf(h4.w, wv[j][2].w, accHN[i][j]);
                    }
                }
            }
        }
        // x-projection part (k in [256,320)): accumulates into accXN for the n gate.
#pragma unroll
        for (int k = HDIM; k < KDIM; k += 4) {
            float4 hv[4];
            hv[0] = *(const float4*)(hr + k);
            hv[1] = *(const float4*)(hr + 16 * HP + k);
            hv[2] = *(const float4*)(hr + 32 * HP + k);
            hv[3] = *(const float4*)(hr + 48 * HP + k);
            float4 wv[2][3];
            wv[0][0] = *(const float4*)(w0 + k);
            wv[0][1] = *(const float4*)(w0 + HP + k);
            wv[0][2] = *(const float4*)(w0 + 2 * HP + k);
            wv[1][0] = *(const float4*)(w1 + k);
            wv[1][1] = *(const float4*)(w1 + HP + k);
            wv[1][2] = *(const float4*)(w1 + 2 * HP + k);
#pragma unroll
            for (int i = 0; i < 4; i++) {
                const float4 h4 = hv[i];
#pragma unroll
                for (int j = 0; j < 2; j++) {
                    accR[i][j]  = fmaf(h4.x, wv[j][0].x, accR[i][j]);
                    accR[i][j]  = fmaf(h4.y, wv[j][0].y, accR[i][j]);
                    accR[i][j]  = fmaf(h4.z, wv[j][0].z, accR[i][j]);
                    accR[i][j]  = fmaf(h4.w, wv[j][0].w, accR[i][j]);
                    accZ[i][j]  = fmaf(h4.x, wv[j][1].x, accZ[i][j]);
                    accZ[i][j]  = fmaf(h4.y, wv[j][1].y, accZ[i][j]);
                    accZ[i][j]  = fmaf(h4.z, wv[j][1].z, accZ[i][j]);
                    accZ[i][j]  = fmaf(h4.w, wv[j][1].w, accZ[i][j]);
                    accXN[i][j] = fmaf(h4.x, wv[j][2].x, accXN[i][j]);
                    accXN[i][j] = fmaf(h4.y, wv[j][2].y, accXN[i][j]);
                    accXN[i][j] = fmaf(h4.z, wv[j][2].z, accXN[i][j]);
                    accXN[i][j] = fmaf(h4.w, wv[j][2].w, accXN[i][j]);
                }
            }
        }

        // ---- Gate epilogue + h update ----
        float* hout = g_h[(t + 1) & 1];
#pragma unroll
        for (int i = 0; i < 4; i++) {
            int row = rg + 16 * i;
#pragma unroll
            for (int j = 0; j < 2; j++) {
                int u = ug + 8 * j;
                float r = sigmoidf_fast(accR[i][j] + bR[j]);
                float z = sigmoidf_fast(accZ[i][j] + bZ[j]);
                float n = tanhf(accXN[i][j] + bIN[j] + r * (accHN[i][j] + bHN[j]));
                float hold = (t > 0) ? h_sm[row * HP + jb * JTILE + u] : 0.f;
                float hnew = (1.f - z) * n + z * hold;
                hout[(size_t)(mb * MTILE + row) * HDIM + jb * JTILE + u] = hnew;
            }
        }

        // ---- Per-batch-group barrier (16 CTAs). __threadfence() => gpu-scope
        // release + CCTL.IVALL (L1 invalidate), so next step's reads are fresh. ----
        bar_i++;
        __threadfence();
        __syncthreads();
        if (tid == 0) {
            const unsigned target = bar_base + bar_i;
            unsigned old = atomicAdd(&g_cnt[mb], 1u);
            if (old == JB_GROUPS - 1) {
                g_cnt[mb] = 0;
                __threadfence();
                *(volatile unsigned*)&g_gen[mb] = target;
            } else {
                while (*(volatile unsigned*)&g_gen[mb] < target) { }
                __threadfence();
            }
        }
        __syncthreads();
    }

    // ---- Output head: p = sigmoid(h_last0 @ w_lin^T + b_lin); out = [p, 1-p] ----
    // Final h lives in g_h[0] (512 steps). One CTA per batch group suffices.
    if (jb == 0) {
        const float* hf = g_h[0] + (size_t)mb * MTILE * HDIM;
        const float bl = __ldg(b_lin);
        for (int row = tid; row < MTILE; row += NTH) {
            const float* hrow = hf + (size_t)row * HDIM;
            float s = bl;
#pragma unroll 8
            for (int k = 0; k < HDIM; k++)
                s = fmaf(__ldcg(hrow + k), __ldg(w_lin + k), s);
            float p = sigmoidf_fast(s);
            int b = mb * MTILE + row;
            out[2 * b]     = p;
            out[2 * b + 1] = 1.f - p;
        }
    }
}

extern "C" void kernel_launch(void* const* d_in, const int* in_sizes, int n_in,
                              void* d_out, int out_size) {
    const float* x     = (const float*)d_in[0];
    const float* w_ih0 = (const float*)d_in[1];
    const float* w_hh0 = (const float*)d_in[2];
    const float* b_ih0 = (const float*)d_in[3];
    const float* b_hh0 = (const float*)d_in[4];
    // d_in[5..8] = layer-1 weights: dead code in the reference (output uses h_last0 only)
    const float* w_lin = (const float*)d_in[9];
    const float* b_lin = (const float*)d_in[10];
    float* out = (float*)d_out;

    const size_t smem = (size_t)(MTILE + WROWS) * HP * sizeof(float);  // 145,152 B
    cudaFuncSetAttribute(gru_fused_kernel,
                         cudaFuncAttributeMaxDynamicSharedMemorySize, (int)smem);

    dim3 grid(JB_GROUPS, MB_GROUPS);  // 16 x 8 = 128 CTAs, 1/SM, all co-resident
    gru_fused_kernel<<<grid, NTH, smem>>>(x, w_ih0, w_hh0, b_ih0, b_hh0,
                                          w_lin, b_lin, out);
}